// round 4
// baseline (speedup 1.0000x reference)
#include <cuda_runtime.h>
#include <math.h>

#define BB 64
#define NN 16384
#define CC 64
#define BPS 8                               // blocks per sample
#define GRID (BB * BPS)                     // 512 persistent blocks
#define THREADS 256
#define NTOT (NN * CC)                      // 1,048,576 floats per sample
#define F4_PER_B (NTOT / 4)                 // 262,144 float4 per sample
#define F4_PER_SLICE (F4_PER_B / BPS)       // 32,768 float4 per block slice
#define ITERS (F4_PER_SLICE / THREADS)      // 128

// __device__ scratch (no allocations allowed)
__device__ float g_psum[BB][BPS][CC];
__device__ float g_psq [BB][BPS][CC];
__device__ unsigned long long g_count = 0ULL;   // monotonic barrier ticket counter

__global__ __launch_bounds__(THREADS, 4) void fused_mixstyle_kernel(
        const float* __restrict__ x,
        const float* __restrict__ alpha_u,
        const float* __restrict__ noise,
        const int*   __restrict__ dom,
        const int*   __restrict__ cls,
        float* __restrict__ out) {
    const int b    = blockIdx.x / BPS;
    const int slab = blockIdx.x % BPS;
    const int tid  = threadIdx.x;
    const float4* __restrict__ x4 = reinterpret_cast<const float4*>(x);
    float4* __restrict__ o4 = reinterpret_cast<float4*>(out);
    const long base = (long)b * F4_PER_B + (long)slab * F4_PER_SLICE;

    __shared__ float4 ssum[THREADS];
    __shared__ float4 ssq [THREADS];
    __shared__ float  s_scale[CC];
    __shared__ float  s_bias [CC];
    __shared__ int    s_idx;

    // ---------------- Phase 1: partial stats, ascending stream ----------------
    float4 s = make_float4(0.f, 0.f, 0.f, 0.f);
    float4 q = make_float4(0.f, 0.f, 0.f, 0.f);
    #pragma unroll 8
    for (int k = 0; k < ITERS; k++) {
        float4 v = __ldg(&x4[base + (long)k * THREADS + tid]);
        s.x += v.x; s.y += v.y; s.z += v.z; s.w += v.w;
        q.x = fmaf(v.x, v.x, q.x);
        q.y = fmaf(v.y, v.y, q.y);
        q.z = fmaf(v.z, v.z, q.z);
        q.w = fmaf(v.w, v.w, q.w);
    }
    ssum[tid] = s;
    ssq [tid] = q;
    __syncthreads();

    if (tid < 16) {   // 16 channel-quads; fold 16 partials each
        float4 S = make_float4(0.f, 0.f, 0.f, 0.f);
        float4 Q = make_float4(0.f, 0.f, 0.f, 0.f);
        #pragma unroll
        for (int m = 0; m < 16; m++) {
            float4 a = ssum[tid + 16 * m];
            float4 c = ssq [tid + 16 * m];
            S.x += a.x; S.y += a.y; S.z += a.z; S.w += a.w;
            Q.x += c.x; Q.y += c.y; Q.z += c.z; Q.w += c.w;
        }
        const int c0 = tid * 4;
        g_psum[b][slab][c0 + 0] = S.x;
        g_psum[b][slab][c0 + 1] = S.y;
        g_psum[b][slab][c0 + 2] = S.z;
        g_psum[b][slab][c0 + 3] = S.w;
        g_psq [b][slab][c0 + 0] = Q.x;
        g_psq [b][slab][c0 + 1] = Q.y;
        g_psq [b][slab][c0 + 2] = Q.z;
        g_psq [b][slab][c0 + 3] = Q.w;
        __threadfence();   // make partials visible device-wide before arrive
    }
    __syncthreads();

    // ---------------- Grid barrier (ticket/generation, replay-safe) ----------
    if (tid == 0) {
        unsigned long long ticket = atomicAdd(&g_count, 1ULL);
        unsigned long long target = (ticket / (unsigned long long)GRID + 1ULL)
                                    * (unsigned long long)GRID;
        for (;;) {
            unsigned long long v;
            asm volatile("ld.global.acquire.gpu.u64 %0, [%1];"
                         : "=l"(v) : "l"(&g_count) : "memory");
            if (v >= target) break;
            __nanosleep(128);
        }
        __threadfence();
    }
    __syncthreads();

    // ---------------- Finalize: partner idx + scale/bias for sample b --------
    if (tid == 0) {
        const int cb = cls[b];
        const int db = dom[b];
        float best = -INFINITY;
        int bi = -1;
        #pragma unroll 1
        for (int j = 0; j < BB; j++) {
            if (cls[j] == cb && dom[j] != db) {
                float v = noise[b * BB + j];
                if (v > best) { best = v; bi = j; }  // strict > == first-max tie-break
            }
        }
        s_idx = (bi < 0) ? b : bi;
    }
    __syncthreads();

    if (tid < CC) {
        const int idx = s_idx;
        const int c = tid;
        float sum = 0.f, sq = 0.f, sum2 = 0.f, sq2 = 0.f;
        #pragma unroll
        for (int sl = 0; sl < BPS; sl++) {
            sum  += g_psum[b][sl][c];
            sq   += g_psq [b][sl][c];
            sum2 += g_psum[idx][sl][c];
            sq2  += g_psq [idx][sl][c];
        }
        const float inv_n   = 1.0f / 16384.0f;
        const float inv_nm1 = 1.0f / 16383.0f;
        const float eps = 1e-6f;

        float mu   = sum * inv_n;
        float var  = (sq  - sum  * sum  * inv_n) * inv_nm1;
        float sig  = sqrtf(var + eps);
        float mu2  = sum2 * inv_n;
        float var2 = (sq2 - sum2 * sum2 * inv_n) * inv_nm1;
        float sig2 = sqrtf(var2 + eps);

        float a = alpha_u[b] * 0.5f;   // ALPHA_MAX
        float mu_mix  = mu  * a + mu2  * (1.0f - a);
        float sig_mix = sig * a + sig2 * (1.0f - a);

        float sc = sig_mix / sig;
        s_scale[c] = sc;
        s_bias [c] = mu_mix - mu * sc;
    }
    __syncthreads();

    // ---------------- Phase 2: apply, DESCENDING (hit the L2-hot tail first) --
    const int cq = tid & 15;
    const float4 scl = *reinterpret_cast<const float4*>(&s_scale[cq * 4]);
    const float4 bia = *reinterpret_cast<const float4*>(&s_bias [cq * 4]);

    #pragma unroll 4
    for (int k = ITERS - 1; k >= 0; k--) {
        const long i4 = base + (long)k * THREADS + tid;
        float4 v = __ldcs(&x4[i4]);        // dead after this read -> evict-first
        float4 r;
        r.x = fmaf(v.x, scl.x, bia.x);
        r.y = fmaf(v.y, scl.y, bia.y);
        r.z = fmaf(v.z, scl.z, bia.z);
        r.w = fmaf(v.w, scl.w, bia.w);
        __stcs(&o4[i4], r);                // never re-read -> evict-first
    }
}

extern "C" void kernel_launch(void* const* d_in, const int* in_sizes, int n_in,
                              void* d_out, int out_size) {
    const float* x       = (const float*)d_in[0];
    const float* alpha_u = (const float*)d_in[1];
    const float* noise   = (const float*)d_in[2];
    const int*   dom     = (const int*)  d_in[3];
    const int*   cls     = (const int*)  d_in[4];
    float* out = (float*)d_out;

    fused_mixstyle_kernel<<<GRID, THREADS>>>(x, alpha_u, noise, dom, cls, out);
}

// round 5
// speedup vs baseline: 1.0568x; 1.0568x over previous
#include <cuda_runtime.h>
#include <math.h>

#define BB 64
#define NN 16384
#define CC 64
#define SLABS 32
#define NTOT (NN * CC)                 // 1,048,576 floats per sample
#define F4_PER_B (NTOT / 4)            // 262,144 float4 per sample
#define F4_PER_SLAB (F4_PER_B / SLABS) // 8,192 float4 per slab

#define F8_PER_B (NTOT / 8)            // 131,072 float8 per sample (2^17)
#define F8_TOTAL ((long)BB * F8_PER_B) // 8,388,608
#define APPLY_THREADS 256
#define APPLY_ITERS 8
#define APPLY_CHUNK (APPLY_THREADS * APPLY_ITERS)     // 2048 float8 per block
#define APPLY_BLOCKS ((int)(F8_TOTAL / APPLY_CHUNK))  // 4096

// __device__ scratch (no allocations allowed)
__device__ float g_psum[BB][SLABS][CC];
__device__ float g_psq [BB][SLABS][CC];
__device__ float g_scale[BB][CC];
__device__ float g_bias [BB][CC];

// ---- 256-bit vector memory ops (sm_100+) -----------------------------------
__device__ __forceinline__ void ld8_nc(const float* __restrict__ p, float v[8]) {
    asm volatile("ld.global.nc.v8.f32 {%0,%1,%2,%3,%4,%5,%6,%7}, [%8];"
                 : "=f"(v[0]), "=f"(v[1]), "=f"(v[2]), "=f"(v[3]),
                   "=f"(v[4]), "=f"(v[5]), "=f"(v[6]), "=f"(v[7])
                 : "l"(p));
}
__device__ __forceinline__ void st8_cs(float* __restrict__ p, const float v[8]) {
    asm volatile("st.global.cs.v8.f32 [%0], {%1,%2,%3,%4,%5,%6,%7,%8};"
                 :: "l"(p),
                    "f"(v[0]), "f"(v[1]), "f"(v[2]), "f"(v[3]),
                    "f"(v[4]), "f"(v[5]), "f"(v[6]), "f"(v[7])
                 : "memory");
}

// ---------------------------------------------------------------------------
// Kernel 1: partial sums / sums-of-squares per (b, slab, c)   [R3 version,
// measured 42.7us @ 6.4TB/s, occ 91% -- unchanged]
// ---------------------------------------------------------------------------
__global__ __launch_bounds__(256) void stats_partial_kernel(const float* __restrict__ x) {
    const int b    = blockIdx.x / SLABS;
    const int slab = blockIdx.x % SLABS;
    const int tid  = threadIdx.x;
    const float4* __restrict__ x4 = reinterpret_cast<const float4*>(x);
    const long base = (long)b * F4_PER_B + (long)slab * F4_PER_SLAB;

    float4 s = make_float4(0.f, 0.f, 0.f, 0.f);
    float4 q = make_float4(0.f, 0.f, 0.f, 0.f);

    #pragma unroll 8
    for (int k = 0; k < F4_PER_SLAB / 256; k++) {
        float4 v = __ldg(&x4[base + (long)k * 256 + tid]);
        s.x += v.x; s.y += v.y; s.z += v.z; s.w += v.w;
        q.x = fmaf(v.x, v.x, q.x);
        q.y = fmaf(v.y, v.y, q.y);
        q.z = fmaf(v.z, v.z, q.z);
        q.w = fmaf(v.w, v.w, q.w);
    }

    __shared__ float4 ssum[256];
    __shared__ float4 ssq [256];
    ssum[tid] = s;
    ssq [tid] = q;
    __syncthreads();

    if (tid < 16) {
        float4 S = make_float4(0.f, 0.f, 0.f, 0.f);
        float4 Q = make_float4(0.f, 0.f, 0.f, 0.f);
        #pragma unroll
        for (int m = 0; m < 16; m++) {
            float4 a = ssum[tid + 16 * m];
            float4 c = ssq [tid + 16 * m];
            S.x += a.x; S.y += a.y; S.z += a.z; S.w += a.w;
            Q.x += c.x; Q.y += c.y; Q.z += c.z; Q.w += c.w;
        }
        const int c0 = tid * 4;
        g_psum[b][slab][c0 + 0] = S.x;
        g_psum[b][slab][c0 + 1] = S.y;
        g_psum[b][slab][c0 + 2] = S.z;
        g_psum[b][slab][c0 + 3] = S.w;
        g_psq [b][slab][c0 + 0] = Q.x;
        g_psq [b][slab][c0 + 1] = Q.y;
        g_psq [b][slab][c0 + 2] = Q.z;
        g_psq [b][slab][c0 + 3] = Q.w;
    }
}

// ---------------------------------------------------------------------------
// Kernel 2: partner selection + per-(b,c) fused scale/bias. [unchanged]
// ---------------------------------------------------------------------------
__global__ __launch_bounds__(64) void finalize_kernel(const float* __restrict__ alpha_u,
                                                      const float* __restrict__ noise,
                                                      const int*   __restrict__ dom,
                                                      const int*   __restrict__ cls) {
    const int b = blockIdx.x;
    __shared__ int s_idx;

    if (threadIdx.x == 0) {
        const int cb = cls[b];
        const int db = dom[b];
        float best = -INFINITY;
        int bi = -1;
        #pragma unroll 1
        for (int j = 0; j < BB; j++) {
            if (cls[j] == cb && dom[j] != db) {
                float v = noise[b * BB + j];
                if (v > best) { best = v; bi = j; }  // strict > == first-max tie-break
            }
        }
        s_idx = (bi < 0) ? b : bi;
    }
    __syncthreads();
    const int idx = s_idx;
    const int c = threadIdx.x;

    float sum = 0.f, sq = 0.f, sum2 = 0.f, sq2 = 0.f;
    #pragma unroll
    for (int s = 0; s < SLABS; s++) {
        sum  += g_psum[b][s][c];
        sq   += g_psq [b][s][c];
        sum2 += g_psum[idx][s][c];
        sq2  += g_psq [idx][s][c];
    }

    const float inv_n   = 1.0f / 16384.0f;
    const float inv_nm1 = 1.0f / 16383.0f;
    const float eps = 1e-6f;

    float mu   = sum * inv_n;
    float var  = (sq  - sum  * sum  * inv_n) * inv_nm1;
    float sig  = sqrtf(var + eps);
    float mu2  = sum2 * inv_n;
    float var2 = (sq2 - sum2 * sum2 * inv_n) * inv_nm1;
    float sig2 = sqrtf(var2 + eps);

    float a = alpha_u[b] * 0.5f;   // ALPHA_MAX
    float mu_mix  = mu  * a + mu2  * (1.0f - a);
    float sig_mix = sig * a + sig2 * (1.0f - a);

    float sc = sig_mix / sig;
    g_scale[b][c] = sc;
    g_bias [b][c] = mu_mix - mu * sc;
}

// ---------------------------------------------------------------------------
// Kernel 3: out = x * scale[b][c] + bias[b][c], 256-bit vector stream.
// Each thread owns a fixed channel-octet (tid & 7) -> scale/bias in registers.
// ---------------------------------------------------------------------------
__global__ __launch_bounds__(APPLY_THREADS) void apply_kernel(const float* __restrict__ x,
                                                              float* __restrict__ out) {
    const long base = (long)blockIdx.x * APPLY_CHUNK;   // in float8 units
    const int  tid  = threadIdx.x;
    const int  b    = (int)(base >> 17);                // / F8_PER_B
    const int  cq8  = tid & 7;                          // channel octet

    float scl[8], bia[8];
    #pragma unroll
    for (int i = 0; i < 8; i++) {
        scl[i] = g_scale[b][cq8 * 8 + i];
        bia[i] = g_bias [b][cq8 * 8 + i];
    }

    #pragma unroll
    for (int k = 0; k < APPLY_ITERS; k++) {
        const long i8 = base + (long)k * APPLY_THREADS + tid;
        const float* p = x + i8 * 8;
        float v[8], r[8];
        ld8_nc(p, v);
        #pragma unroll
        for (int i = 0; i < 8; i++) r[i] = fmaf(v[i], scl[i], bia[i]);
        st8_cs(out + i8 * 8, r);
    }
}

extern "C" void kernel_launch(void* const* d_in, const int* in_sizes, int n_in,
                              void* d_out, int out_size) {
    const float* x       = (const float*)d_in[0];
    const float* alpha_u = (const float*)d_in[1];
    const float* noise   = (const float*)d_in[2];
    const int*   dom     = (const int*)  d_in[3];
    const int*   cls     = (const int*)  d_in[4];
    float* out = (float*)d_out;

    stats_partial_kernel<<<BB * SLABS, 256>>>(x);
    finalize_kernel<<<BB, CC>>>(alpha_u, noise, dom, cls);
    apply_kernel<<<APPLY_BLOCKS, APPLY_THREADS>>>(x, out);
}